// round 1
// baseline (speedup 1.0000x reference)
#include <cuda_runtime.h>

// y[m, i2*32+i1] = sum_{j2,j1} x[m, j2*32+j1] * W2[i2,j2] * W1[i1,j1] + bias
// Factorized per row:  T = X @ W1^T ;  Y = W2 @ T  (two 32x32x32 GEMMs)
// One warp per row. Packed f32x2 FMA (sm_103a) for 2x fp32 throughput.

typedef unsigned long long u64;

__device__ __forceinline__ u64 ffma2(u64 a, u64 b, u64 c) {
    u64 d;
    asm("fma.rn.f32x2 %0, %1, %2, %3;" : "=l"(d) : "l"(a), "l"(b), "l"(c));
    return d;
}
__device__ __forceinline__ u64 dup2(float x) {
    u64 d;
    asm("mov.b64 %0, {%1, %1};" : "=l"(d) : "f"(x));
    return d;
}
__device__ __forceinline__ u64 pack2(float a, float b) {
    u64 d;
    asm("mov.b64 %0, {%1, %2};" : "=l"(d) : "f"(a), "f"(b));
    return d;
}
__device__ __forceinline__ void unpack2(u64 v, float& a, float& b) {
    asm("mov.b64 {%0, %1}, %2;" : "=f"(a), "=f"(b) : "l"(v));
}

#define WARPS 8
#define TSTRIDE 36   // padded row stride (floats): conflict-free STS.128 / LDS.32

__global__ void __launch_bounds__(WARPS * 32)
kron_mlp_kernel(const float* __restrict__ x,
                const float* __restrict__ w1,
                const float* __restrict__ w2,
                const float* __restrict__ bias,
                float* __restrict__ out,
                int rows)
{
    __shared__ __align__(16) float sW1T[1024];             // [j1][i1] = W1[i1][j1]
    __shared__ __align__(16) float sW2T[1024];             // [j2][i2] = W2[i2][j2]
    __shared__ __align__(16) float sT[WARPS][32 * TSTRIDE];

    const int tid  = threadIdx.x;
    const int lane = tid & 31;
    const int warp = tid >> 5;

    // Load weights transposed into smem (pairs along the packed (i) dim contiguous)
    for (int i = tid; i < 1024; i += WARPS * 32) {
        int r = i >> 5, c = i & 31;          // w[r][c]
        sW1T[c * 32 + r] = w1[i];
        sW2T[c * 32 + r] = w2[i];
    }
    // Per-thread packed bias: rb[p] = (bias[(2p)*32+lane], bias[(2p+1)*32+lane])
    u64 rb[16];
#pragma unroll
    for (int p = 0; p < 16; p++)
        rb[p] = pack2(bias[(2 * p) * 32 + lane], bias[(2 * p + 1) * 32 + lane]);
    __syncthreads();

    float* myT = sT[warp];
    const int gwarp  = blockIdx.x * WARPS + warp;
    const int nwarps = gridDim.x * WARPS;

    for (int m = gwarp; m < rows; m += nwarps) {
        // ---- Load X row j2 = lane : 8x LDG.128, warp covers contiguous 4KB ----
        float X[32];
        const float4* xr =
            reinterpret_cast<const float4*>(x + (size_t)m * 1024 + lane * 32);
#pragma unroll
        for (int k = 0; k < 8; k++) {
            float4 v = xr[k];
            X[4 * k + 0] = v.x; X[4 * k + 1] = v.y;
            X[4 * k + 2] = v.z; X[4 * k + 3] = v.w;
        }

        // ---- Stage 1: T[lane][i1] = sum_j1 X[lane][j1] * W1[i1][j1] ----
        u64 acc[16];
#pragma unroll
        for (int p = 0; p < 16; p++) acc[p] = 0ull;   // packed (0.f, 0.f)
#pragma unroll
        for (int j1 = 0; j1 < 32; j1++) {
            u64 xv = dup2(X[j1]);
            const u64* w = reinterpret_cast<const u64*>(sW1T + j1 * 32);
#pragma unroll
            for (int p = 0; p < 16; p++) acc[p] = ffma2(xv, w[p], acc[p]);
        }

        // ---- Transpose T through padded smem ----
        {
            float4* dst = reinterpret_cast<float4*>(myT + lane * TSTRIDE);
#pragma unroll
            for (int p = 0; p < 8; p++) {
                float4 v;
                unpack2(acc[2 * p],     v.x, v.y);
                unpack2(acc[2 * p + 1], v.z, v.w);
                dst[p] = v;
            }
        }
        __syncwarp();
        float Tc[32];
#pragma unroll
        for (int j2 = 0; j2 < 32; j2++) Tc[j2] = myT[j2 * TSTRIDE + lane];
        __syncwarp();

        // ---- Stage 2: Y[i2][lane] = bias + sum_j2 W2[i2][j2] * T[j2][lane] ----
        u64 acc2[16];
#pragma unroll
        for (int p = 0; p < 16; p++) acc2[p] = rb[p];  // bias folded into init
#pragma unroll
        for (int j2 = 0; j2 < 32; j2++) {
            u64 tv = dup2(Tc[j2]);
            const u64* w = reinterpret_cast<const u64*>(sW2T + j2 * 32);
#pragma unroll
            for (int p = 0; p < 16; p++) acc2[p] = ffma2(tv, w[p], acc2[p]);
        }

        // ---- Write out: out[m*1024 + i2*32 + lane], coalesced per i2 ----
        float* orow = out + (size_t)m * 1024 + lane;
#pragma unroll
        for (int p = 0; p < 16; p++) {
            float a, b;
            unpack2(acc2[p], a, b);
            orow[(2 * p) * 32]     = a;
            orow[(2 * p + 1) * 32] = b;
        }
    }
}

extern "C" void kernel_launch(void* const* d_in, const int* in_sizes, int n_in,
                              void* d_out, int out_size) {
    const float* x    = (const float*)d_in[0];
    const float* w1   = (const float*)d_in[1];
    const float* w2   = (const float*)d_in[2];
    const float* bias = (const float*)d_in[3];
    float* out        = (float*)d_out;

    int rows = in_sizes[0] / 1024;          // B*S = 65536
    int grid = 592;                          // ~4 CTAs/SM worth of work queue
    int maxg = (rows + WARPS - 1) / WARPS;
    if (grid > maxg) grid = maxg;

    kron_mlp_kernel<<<grid, WARPS * 32>>>(x, w1, w2, bias, out, rows);
}

// round 2
// speedup vs baseline: 1.9854x; 1.9854x over previous
#include <cuda_runtime.h>

// y[m, i2*32+i1] = sum_{j2,j1} x[m, j2*32+j1] * W2[i2,j2] * W1[i1,j1] + bias
// Per row m:  T = X @ W1^T ;  Y = W2 @ T   (two 32x32x32 GEMMs)
// One warp per row; register-blocked micro-GEMM: each lane owns a 4x8 tile,
// so 3 LDS.128 feed 16 ffma2 (32 FMAs). Packed f32x2 FMA for 2x fp32 tput.

typedef unsigned long long u64;

__device__ __forceinline__ u64 ffma2(u64 a, u64 b, u64 c) {
    u64 d;
    asm("fma.rn.f32x2 %0, %1, %2, %3;" : "=l"(d) : "l"(a), "l"(b), "l"(c));
    return d;
}
__device__ __forceinline__ u64 dup2(float x) {
    u64 d;
    asm("mov.b64 %0, {%1, %1};" : "=l"(d) : "f"(x));
    return d;
}
__device__ __forceinline__ u64 pack2(float a, float b) {
    u64 d;
    asm("mov.b64 %0, {%1, %2};" : "=l"(d) : "f"(a), "f"(b));
    return d;
}

#define WARPS 4

__global__ void __launch_bounds__(WARPS * 32)
kron_mlp_kernel(const float* __restrict__ x,
                const float* __restrict__ w1,
                const float* __restrict__ w2,
                const float* __restrict__ bias,
                float* __restrict__ out,
                int rows)
{
    __shared__ __align__(16) float sW1T[1024];          // [k][i1]  = W1[i1][k]
    __shared__ __align__(16) float sW2T[1024];          // [j2][i2] = W2[i2][j2]
    __shared__ __align__(16) float sBuf[WARPS][1024];   // XT[k][j2], then T (swizzled)

    const int tid  = threadIdx.x;
    const int lane = tid & 31;
    const int warp = tid >> 5;
    const int a = lane & 7;     // row-block   (j2 or i2): rows 4a..4a+3
    const int b = lane >> 3;    // col-block   (i1):       cols 8b..8b+7

    // Weights transposed into smem (once per CTA)
    for (int i = tid; i < 1024; i += WARPS * 32) {
        int r = i >> 5, c = i & 31;            // w[r][c]
        sW1T[c * 32 + r] = w1[i];
        sW2T[c * 32 + r] = w2[i];
    }

    // Packed bias for this lane's output tile: rb[ia*4+pb] covers
    // out cols i1 = 8b+2pb .. +1 of row i2 = 4a+ia.
    u64 rb[16];
#pragma unroll
    for (int ia = 0; ia < 4; ia++)
#pragma unroll
        for (int pb = 0; pb < 4; pb++) {
            int i1 = 8 * b + 2 * pb;
            rb[ia * 4 + pb] = pack2(bias[(4 * a + ia) * 32 + i1],
                                    bias[(4 * a + ia) * 32 + i1 + 1]);
        }
    __syncthreads();

    float* buf = sBuf[warp];
    const int gw = blockIdx.x * WARPS + warp;
    const int nw = gridDim.x * WARPS;

    for (int m = gw; m < rows; m += nw) {
        // ---- Load X row (coalesced LDG.128) and transpose into buf:
        //      buf[k*32 + j2] = X[j2][k]   (conflict-free STS.32) ----
        {
            const float4* xr =
                reinterpret_cast<const float4*>(x + (size_t)m * 1024 + lane * 32);
#pragma unroll
            for (int q = 0; q < 8; q++) {
                float4 v = xr[q];
                buf[(4 * q + 0) * 32 + lane] = v.x;
                buf[(4 * q + 1) * 32 + lane] = v.y;
                buf[(4 * q + 2) * 32 + lane] = v.z;
                buf[(4 * q + 3) * 32 + lane] = v.w;
            }
        }
        __syncwarp();

        // ---- Stage 1: T[j2][i1] = sum_k X[j2][k] * W1[i1][k] ----
        // lane tile: j2 in 4a..4a+3, i1 in 8b..8b+7
        u64 acc[16];
#pragma unroll
        for (int i = 0; i < 16; i++) acc[i] = 0ull;
#pragma unroll
        for (int k = 0; k < 32; k++) {
            float4 af = *reinterpret_cast<const float4*>(&buf[k * 32 + 4 * a]);
            const u64* wq = reinterpret_cast<const u64*>(&sW1T[k * 32 + 8 * b]);
            u64 b0 = wq[0], b1 = wq[1], b2 = wq[2], b3 = wq[3];
            const float* afp = reinterpret_cast<const float*>(&af);
#pragma unroll
            for (int ja = 0; ja < 4; ja++) {
                u64 av = dup2(afp[ja]);
                acc[ja * 4 + 0] = ffma2(av, b0, acc[ja * 4 + 0]);
                acc[ja * 4 + 1] = ffma2(av, b1, acc[ja * 4 + 1]);
                acc[ja * 4 + 2] = ffma2(av, b2, acc[ja * 4 + 2]);
                acc[ja * 4 + 3] = ffma2(av, b3, acc[ja * 4 + 3]);
            }
        }
        __syncwarp();   // all lanes done reading XT before T overwrites buf

        // ---- Store T into buf with quad swizzle: quad' = quad ^ (j2>>2).
        //      Makes both these STS.128 and stage-2 reads conflict-free. ----
#pragma unroll
        for (int ja = 0; ja < 4; ja++) {
            int j2 = 4 * a + ja;   // j2>>2 == a
            ulonglong2 v0 = make_ulonglong2(acc[ja * 4 + 0], acc[ja * 4 + 1]);
            ulonglong2 v1 = make_ulonglong2(acc[ja * 4 + 2], acc[ja * 4 + 3]);
            *reinterpret_cast<ulonglong2*>(
                &buf[j2 * 32 + (((2 * b + 0) ^ a) << 2)]) = v0;
            *reinterpret_cast<ulonglong2*>(
                &buf[j2 * 32 + (((2 * b + 1) ^ a) << 2)]) = v1;
        }
        __syncwarp();

        // ---- Stage 2: Y[i2][i1] = bias + sum_j2 W2[i2][j2] * T[j2][i1] ----
        // lane tile: i2 in 4a..4a+3, i1 in 8b..8b+7
        u64 acc2[16];
#pragma unroll
        for (int i = 0; i < 16; i++) acc2[i] = rb[i];
#pragma unroll
        for (int j2 = 0; j2 < 32; j2++) {
            float4 af = *reinterpret_cast<const float4*>(&sW2T[j2 * 32 + 4 * a]);
            int key = j2 >> 2;
            const u64* t0 = reinterpret_cast<const u64*>(
                &buf[j2 * 32 + (((2 * b + 0) ^ key) << 2)]);
            const u64* t1 = reinterpret_cast<const u64*>(
                &buf[j2 * 32 + (((2 * b + 1) ^ key) << 2)]);
            u64 b0 = t0[0], b1 = t0[1], b2 = t1[0], b3 = t1[1];
            const float* afp = reinterpret_cast<const float*>(&af);
#pragma unroll
            for (int ia = 0; ia < 4; ia++) {
                u64 av = dup2(afp[ia]);
                acc2[ia * 4 + 0] = ffma2(av, b0, acc2[ia * 4 + 0]);
                acc2[ia * 4 + 1] = ffma2(av, b1, acc2[ia * 4 + 1]);
                acc2[ia * 4 + 2] = ffma2(av, b2, acc2[ia * 4 + 2]);
                acc2[ia * 4 + 3] = ffma2(av, b3, acc2[ia * 4 + 3]);
            }
        }

        // ---- Write out: out[m][i2*32 + i1], coalesced STG.128 ----
#pragma unroll
        for (int ia = 0; ia < 4; ia++) {
            float* dst = out + (size_t)m * 1024 + (4 * a + ia) * 32 + 8 * b;
            *reinterpret_cast<ulonglong2*>(dst) =
                make_ulonglong2(acc2[ia * 4 + 0], acc2[ia * 4 + 1]);
            *reinterpret_cast<ulonglong2*>(dst + 4) =
                make_ulonglong2(acc2[ia * 4 + 2], acc2[ia * 4 + 3]);
        }
        __syncwarp();   // all lanes done reading T before next iter's XT write
    }
}

extern "C" void kernel_launch(void* const* d_in, const int* in_sizes, int n_in,
                              void* d_out, int out_size) {
    const float* x    = (const float*)d_in[0];
    const float* w1   = (const float*)d_in[1];
    const float* w2   = (const float*)d_in[2];
    const float* bias = (const float*)d_in[3];
    float* out        = (float*)d_out;

    int rows = in_sizes[0] / 1024;           // B*S = 65536
    int grid = 592;                           // 4 CTAs/SM, one balanced wave
    int maxg = (rows + WARPS - 1) / WARPS;
    if (grid > maxg) grid = maxg;

    kron_mlp_kernel<<<grid, WARPS * 32>>>(x, w1, w2, bias, out, rows);
}

// round 4
// speedup vs baseline: 3.2621x; 1.6431x over previous
#include <cuda_runtime.h>
#include <cuda_bf16.h>
#include <cstdint>

// y[m, i2*32+i1] = sum_{j2,j1} x[m,j2*32+j1] * W2[i2,j2] * W1[i1,j1] + bias
// Per row m (one warp):
//   Stage1: T[j2][i1] = X(32x32) @ W1^T    (mma.sync bf16, 3-term hi/lo split)
//   Stage2: G[i2][i1] = W2 @ T             (same; acc initialized with bias)
// All tensor work via mma.sync.m16n8k16 (baseline PTX, assembles for sm_103).

typedef unsigned int u32;

#define ROWSTRIDE 80          // smem row stride (bytes): conflict-free everywhere
#define PLANE     2560        // 32 rows * 80B  (hi plane -> lo plane offset)

// smem byte offsets (dynamic)
#define SM_W1    0            // B1[j1][i1] = W1[i1][j1], hi @0, lo @+PLANE
#define SM_W2    5120         // A2[i2][j2] = W2 row-major, hi/lo planes
#define SM_BIAS  10240        // float4 per (tile, lane): 8*32*16 = 4096 B
#define SM_WARP  14336        // per warp: Xh, Xl, Th, Tl (4 * 2560 = 10240)
#define WARP_BYTES 10240
#define NWARPS   8
#define SM_TOTAL (SM_WARP + NWARPS * WARP_BYTES)   // 96256 B

extern __shared__ char dsm[];

__device__ __forceinline__ u32 smem_u32(const void* p) {
    u32 a;
    asm("{ .reg .u64 t; cvta.to.shared.u64 t, %1; cvt.u32.u64 %0, t; }"
        : "=r"(a) : "l"(p));
    return a;
}
__device__ __forceinline__ void ldm_x4(u32* r, u32 addr) {
    asm volatile("ldmatrix.sync.aligned.m8n8.x4.shared.b16 {%0,%1,%2,%3}, [%4];"
                 : "=r"(r[0]), "=r"(r[1]), "=r"(r[2]), "=r"(r[3]) : "r"(addr));
}
__device__ __forceinline__ void ldm_x4t(u32* r, u32 addr) {
    asm volatile("ldmatrix.sync.aligned.m8n8.x4.trans.shared.b16 {%0,%1,%2,%3}, [%4];"
                 : "=r"(r[0]), "=r"(r[1]), "=r"(r[2]), "=r"(r[3]) : "r"(addr));
}
__device__ __forceinline__ void mma_bf16(float* c, const u32* a, const u32* b) {
    asm volatile(
        "mma.sync.aligned.m16n8k16.row.col.f32.bf16.bf16.f32 "
        "{%0,%1,%2,%3}, {%4,%5,%6,%7}, {%8,%9}, {%0,%1,%2,%3};"
        : "+f"(c[0]), "+f"(c[1]), "+f"(c[2]), "+f"(c[3])
        : "r"(a[0]), "r"(a[1]), "r"(a[2]), "r"(a[3]), "r"(b[0]), "r"(b[1]));
}
// h = bf16x2(a lo, b hi); l = bf16x2 of residuals
__device__ __forceinline__ void split2(float a, float b, u32& h, u32& l) {
    asm("cvt.rn.bf16x2.f32 %0, %1, %2;" : "=r"(h) : "f"(b), "f"(a));
    float ha = __uint_as_float(h << 16);
    float hb = __uint_as_float(h & 0xFFFF0000u);
    float ra = a - ha, rb = b - hb;
    asm("cvt.rn.bf16x2.f32 %0, %1, %2;" : "=r"(l) : "f"(rb), "f"(ra));
}

// One 32x32x32 GEMM, 3-term split. A row-major @aBase (hi; lo @+PLANE),
// B k-major rows @bBase (hi/lo). acc[(mt*4+nt)*4 + i] f32.
__device__ __forceinline__ void do_stage(u32 aBase, u32 bBase, u32 laneOff,
                                         float* acc) {
    u32 Ah[16], Al[16], Bh[16];
#pragma unroll
    for (int mt = 0; mt < 2; mt++)
#pragma unroll
        for (int kt = 0; kt < 2; kt++) {
            u32 ad = aBase + mt * (16 * ROWSTRIDE) + kt * 32 + laneOff;
            ldm_x4(&Ah[(mt * 2 + kt) * 4], ad);
            ldm_x4(&Al[(mt * 2 + kt) * 4], ad + PLANE);
        }
#pragma unroll
    for (int kt = 0; kt < 2; kt++)
#pragma unroll
        for (int np = 0; np < 2; np++)
            ldm_x4t(&Bh[(kt * 2 + np) * 4],
                    bBase + kt * (16 * ROWSTRIDE) + np * 32 + laneOff);

    // pass 1: Ah * Bh
#pragma unroll
    for (int kt = 0; kt < 2; kt++)
#pragma unroll
        for (int mt = 0; mt < 2; mt++)
#pragma unroll
            for (int np = 0; np < 2; np++) {
                mma_bf16(&acc[(mt * 4 + 2 * np) * 4],
                         &Ah[(mt * 2 + kt) * 4], &Bh[(kt * 2 + np) * 4]);
                mma_bf16(&acc[(mt * 4 + 2 * np + 1) * 4],
                         &Ah[(mt * 2 + kt) * 4], &Bh[(kt * 2 + np) * 4 + 2]);
            }
    // pass 2: Ah * Bl (Bl transient)
#pragma unroll
    for (int kt = 0; kt < 2; kt++)
#pragma unroll
        for (int np = 0; np < 2; np++) {
            u32 bl[4];
            ldm_x4t(bl, bBase + PLANE + kt * (16 * ROWSTRIDE) + np * 32 + laneOff);
#pragma unroll
            for (int mt = 0; mt < 2; mt++) {
                mma_bf16(&acc[(mt * 4 + 2 * np) * 4],
                         &Ah[(mt * 2 + kt) * 4], bl);
                mma_bf16(&acc[(mt * 4 + 2 * np + 1) * 4],
                         &Ah[(mt * 2 + kt) * 4], bl + 2);
            }
        }
    // pass 3: Al * Bh
#pragma unroll
    for (int kt = 0; kt < 2; kt++)
#pragma unroll
        for (int mt = 0; mt < 2; mt++)
#pragma unroll
            for (int np = 0; np < 2; np++) {
                mma_bf16(&acc[(mt * 4 + 2 * np) * 4],
                         &Al[(mt * 2 + kt) * 4], &Bh[(kt * 2 + np) * 4]);
                mma_bf16(&acc[(mt * 4 + 2 * np + 1) * 4],
                         &Al[(mt * 2 + kt) * 4], &Bh[(kt * 2 + np) * 4 + 2]);
            }
}

__global__ void __launch_bounds__(NWARPS * 32, 2)
kron_mma_kernel(const float* __restrict__ x,
                const float* __restrict__ w1,
                const float* __restrict__ w2,
                const float* __restrict__ bias,
                float* __restrict__ out,
                int rows)
{
    const int tid  = threadIdx.x;
    const int lane = tid & 31;
    const int wrp  = tid >> 5;
    const u32 sb   = smem_u32(dsm);

    // ldmatrix lane offset: group g = lane>>3 selects tile; rows within tile.
    const u32 laneOff = ((lane & 7) + 8 * ((lane >> 3) & 1)) * ROWSTRIDE +
                        ((lane >> 4) << 4);
    const int qr = lane >> 2;          // c-fragment row within 16-tile
    const int qc = (lane & 3) << 1;    // c-fragment col pair base

    // ---- one-time: weights + bias into smem ----
    if (wrp == 0) {  // B1[j1][i1] = W1[i1][j1]; lane = j1
        float v[32];
#pragma unroll
        for (int i1 = 0; i1 < 32; i1++) v[i1] = w1[i1 * 32 + lane];
        u32 hw[16], lw[16];
#pragma unroll
        for (int p = 0; p < 16; p++) split2(v[2 * p], v[2 * p + 1], hw[p], lw[p]);
        char* rb = dsm + SM_W1 + lane * ROWSTRIDE;
#pragma unroll
        for (int c = 0; c < 4; c++) {
            *(uint4*)(rb + c * 16) =
                make_uint4(hw[4 * c], hw[4 * c + 1], hw[4 * c + 2], hw[4 * c + 3]);
            *(uint4*)(rb + PLANE + c * 16) =
                make_uint4(lw[4 * c], lw[4 * c + 1], lw[4 * c + 2], lw[4 * c + 3]);
        }
    } else if (wrp == 1) {  // A2 = W2 row-major; lane = i2
        float v[32];
        const float4* wr = (const float4*)(w2 + lane * 32);
#pragma unroll
        for (int q = 0; q < 8; q++) {
            float4 t = wr[q];
            v[4 * q] = t.x; v[4 * q + 1] = t.y; v[4 * q + 2] = t.z; v[4 * q + 3] = t.w;
        }
        u32 hw[16], lw[16];
#pragma unroll
        for (int p = 0; p < 16; p++) split2(v[2 * p], v[2 * p + 1], hw[p], lw[p]);
        char* rb = dsm + SM_W2 + lane * ROWSTRIDE;
#pragma unroll
        for (int c = 0; c < 4; c++) {
            *(uint4*)(rb + c * 16) =
                make_uint4(hw[4 * c], hw[4 * c + 1], hw[4 * c + 2], hw[4 * c + 3]);
            *(uint4*)(rb + PLANE + c * 16) =
                make_uint4(lw[4 * c], lw[4 * c + 1], lw[4 * c + 2], lw[4 * c + 3]);
        }
    }
    // bias, permuted to c-fragment order: one float4 per (tile t8, lane)
    {
        int t8 = tid >> 5, ln = tid & 31;
        int mt = t8 >> 2, nt = t8 & 3;
        int r = 16 * mt + (ln >> 2), c = 8 * nt + ((ln & 3) << 1);
        ((float4*)(dsm + SM_BIAS))[t8 * 32 + ln] =
            make_float4(bias[r * 32 + c], bias[r * 32 + c + 1],
                        bias[(r + 8) * 32 + c], bias[(r + 8) * 32 + c + 1]);
    }
    __syncthreads();

    const u32 xBase = sb + SM_WARP + wrp * WARP_BYTES;          // X hi
    const u32 tBase = xBase + 2 * PLANE;                        // T hi
    const u32 b1Base = sb + SM_W1;
    const u32 a2Base = sb + SM_W2;
    const float4* sbias4 = (const float4*)(dsm + SM_BIAS);
    char* xPtr = dsm + SM_WARP + wrp * WARP_BYTES;
    char* tPtr = xPtr + 2 * PLANE;

    const int gw = blockIdx.x * NWARPS + wrp;
    const int nw = gridDim.x * NWARPS;

    for (int m = gw; m < rows; m += nw) {
        // ---- load X row (lane = j2), split, store to Xbuf ----
        {
            const float4* xr = (const float4*)(x + (size_t)m * 1024 + lane * 32);
            u32 hw[16], lw[16];
#pragma unroll
            for (int q = 0; q < 8; q++) {
                float4 v = xr[q];
                split2(v.x, v.y, hw[2 * q], lw[2 * q]);
                split2(v.z, v.w, hw[2 * q + 1], lw[2 * q + 1]);
            }
            char* rb = xPtr + lane * ROWSTRIDE;
#pragma unroll
            for (int c = 0; c < 4; c++) {
                *(uint4*)(rb + c * 16) =
                    make_uint4(hw[4 * c], hw[4 * c + 1], hw[4 * c + 2], hw[4 * c + 3]);
                *(uint4*)(rb + PLANE + c * 16) =
                    make_uint4(lw[4 * c], lw[4 * c + 1], lw[4 * c + 2], lw[4 * c + 3]);
            }
        }
        __syncwarp();

        // ---- stage 1: T = X @ W1^T ----
        float acc[32];
#pragma unroll
        for (int i = 0; i < 32; i++) acc[i] = 0.f;
        do_stage(xBase, b1Base, laneOff, acc);

        // ---- epilogue 1: split T, store row-major (j2 x i1) ----
#pragma unroll
        for (int mt = 0; mt < 2; mt++)
#pragma unroll
            for (int nt = 0; nt < 4; nt++) {
                float* c = &acc[(mt * 4 + nt) * 4];
                u32 h01, l01, h23, l23;
                split2(c[0], c[1], h01, l01);
                split2(c[2], c[3], h23, l23);
                int off = (16 * mt + qr) * ROWSTRIDE + (8 * nt + qc) * 2;
                *(u32*)(tPtr + off) = h01;
                *(u32*)(tPtr + PLANE + off) = l01;
                off += 8 * ROWSTRIDE;
                *(u32*)(tPtr + off) = h23;
                *(u32*)(tPtr + PLANE + off) = l23;
            }
        __syncwarp();

        // ---- stage 2: G = W2 @ T, acc init = bias (permuted) ----
#pragma unroll
        for (int t8 = 0; t8 < 8; t8++) {
            float4 b4 = sbias4[t8 * 32 + lane];
            acc[t8 * 4 + 0] = b4.x; acc[t8 * 4 + 1] = b4.y;
            acc[t8 * 4 + 2] = b4.z; acc[t8 * 4 + 3] = b4.w;
        }
        do_stage(a2Base, tBase, laneOff, acc);

        // ---- write out[m][i2*32+i1] ----
        float* ob = out + (size_t)m * 1024;
#pragma unroll
        for (int mt = 0; mt < 2; mt++)
#pragma unroll
            for (int nt = 0; nt < 4; nt++) {
                float* c = &acc[(mt * 4 + nt) * 4];
                int i2 = 16 * mt + qr, i1 = 8 * nt + qc;
                *(float2*)(ob + i2 * 32 + i1) = make_float2(c[0], c[1]);
                *(float2*)(ob + (i2 + 8) * 32 + i1) = make_float2(c[2], c[3]);
            }
        __syncwarp();
    }
}

extern "C" void kernel_launch(void* const* d_in, const int* in_sizes, int n_in,
                              void* d_out, int out_size) {
    const float* x    = (const float*)d_in[0];
    const float* w1   = (const float*)d_in[1];
    const float* w2   = (const float*)d_in[2];
    const float* bias = (const float*)d_in[3];
    float* out        = (float*)d_out;

    int rows = in_sizes[0] / 1024;   // 65536

    cudaFuncSetAttribute(kron_mma_kernel,
                         cudaFuncAttributeMaxDynamicSharedMemorySize, SM_TOTAL);

    int grid = 296;                  // 2 CTAs/SM, persistent grid-stride
    int maxg = (rows + NWARPS - 1) / NWARPS;
    if (grid > maxg) grid = maxg;
    kron_mma_kernel<<<grid, NWARPS * 32, SM_TOTAL>>>(x, w1, w2, bias, out, rows);
}

// round 6
// speedup vs baseline: 3.5013x; 1.0733x over previous
#include <cuda_runtime.h>
#include <cuda_bf16.h>
#include <cstdint>

// y[m, i2*32+i1] = sum_{j2,j1} x[m,j2*32+j1] * W2[i2,j2] * W1[i1,j1] + bias
// Per row m (one warp):
//   Stage1: T[j2][i1] = X @ W1^T   (A = X frags from smem, B = W1^T frags IN REGS)
//   Stage2: G[i2][i1] = W2 @ T     (A = W2 frags IN REGS,  B = T frags from smem)
// mma.sync.m16n8k16 bf16, fp32 accuracy via 3-term hi/lo split.

typedef unsigned int u32;

#define RS 80                 // X/T smem row stride (bytes), conflict-free
#define GS 160                // G (fp32 32x32) row stride (bytes), conflict-free
#define XH 0                  // per-warp buffer offsets
#define XL 2560
#define TH 5120
#define TL 7680
#define WBYTES 10240          // per-warp buffer (G overlays XH..XL: 32*160=5120)
#define NW 4                  // warps per CTA

__shared__ __align__(16) char sbuf[NW * WBYTES];
__shared__ __align__(16) float sbias[1024];

__device__ __forceinline__ u32 smem_u32(const void* p) {
    u32 a;
    asm("{ .reg .u64 t; cvta.to.shared.u64 t, %1; cvt.u32.u64 %0, t; }"
        : "=r"(a) : "l"(p));
    return a;
}
__device__ __forceinline__ void ldm_x4(u32* r, u32 addr) {
    asm volatile("ldmatrix.sync.aligned.m8n8.x4.shared.b16 {%0,%1,%2,%3}, [%4];"
                 : "=r"(r[0]), "=r"(r[1]), "=r"(r[2]), "=r"(r[3]) : "r"(addr));
}
__device__ __forceinline__ void ldm_x4t(u32* r, u32 addr) {
    asm volatile("ldmatrix.sync.aligned.m8n8.x4.trans.shared.b16 {%0,%1,%2,%3}, [%4];"
                 : "=r"(r[0]), "=r"(r[1]), "=r"(r[2]), "=r"(r[3]) : "r"(addr));
}
__device__ __forceinline__ void mma_bf16(float* c, const u32* a, const u32* b) {
    asm volatile(
        "mma.sync.aligned.m16n8k16.row.col.f32.bf16.bf16.f32 "
        "{%0,%1,%2,%3}, {%4,%5,%6,%7}, {%8,%9}, {%0,%1,%2,%3};"
        : "+f"(c[0]), "+f"(c[1]), "+f"(c[2]), "+f"(c[3])
        : "r"(a[0]), "r"(a[1]), "r"(a[2]), "r"(a[3]), "r"(b[0]), "r"(b[1]));
}
// h = bf16x2(a low half, b high half); l = residuals
__device__ __forceinline__ void split2(float a, float b, u32& h, u32& l) {
    asm("cvt.rn.bf16x2.f32 %0, %1, %2;" : "=r"(h) : "f"(b), "f"(a));
    float ha = __uint_as_float(h << 16);
    float hb = __uint_as_float(h & 0xFFFF0000u);
    float ra = a - ha, rb = b - hb;
    asm("cvt.rn.bf16x2.f32 %0, %1, %2;" : "=r"(l) : "f"(rb), "f"(ra));
}
// split a 32-float row (8 float4), store hi/lo 64B rows at rowPtr / rowPtr+plane
__device__ __forceinline__ void split_store_row(char* rowPtr, int planeOff,
                                                const float4* v) {
    u32 hw[16], lw[16];
#pragma unroll
    for (int q = 0; q < 8; q++) {
        split2(v[q].x, v[q].y, hw[2 * q], lw[2 * q]);
        split2(v[q].z, v[q].w, hw[2 * q + 1], lw[2 * q + 1]);
    }
#pragma unroll
    for (int c = 0; c < 4; c++) {
        *(uint4*)(rowPtr + c * 16) =
            make_uint4(hw[4 * c], hw[4 * c + 1], hw[4 * c + 2], hw[4 * c + 3]);
        *(uint4*)(rowPtr + planeOff + c * 16) =
            make_uint4(lw[4 * c], lw[4 * c + 1], lw[4 * c + 2], lw[4 * c + 3]);
    }
}

__global__ void __launch_bounds__(NW * 32)
kron_mma2_kernel(const float* __restrict__ x,
                 const float* __restrict__ w1,
                 const float* __restrict__ w2,
                 const float* __restrict__ bias,
                 float* __restrict__ out,
                 int rows)
{
    const int tid  = threadIdx.x;
    const int lane = tid & 31;
    const int wrp  = tid >> 5;
    char* wbuf  = sbuf + wrp * WBYTES;
    const u32 wbA = smem_u32(wbuf);

    // ldmatrix lane offset: rows (lane&7)+8*bit3 (stride RS), +16B col for lanes>=16
    const u32 laneOff = ((lane & 7) + 8 * ((lane >> 3) & 1)) * RS +
                        ((lane >> 4) << 4);
    const int qr = lane >> 2;           // c-frag row within 16-row tile
    const int qc = (lane & 3) << 1;     // c-frag col pair base

    // ---- one-time: stage W1/W2 split planes into warp0's buffer region ----
    // layout: W1h@0, W1l@2560, W2h@5120, W2l@7680 (row stride RS)
    if (wrp == 0) {
        float4 v[8];
        const float4* r = (const float4*)(w1 + lane * 32);
#pragma unroll
        for (int q = 0; q < 8; q++) v[q] = r[q];
        split_store_row(sbuf + 0 + lane * RS, 2560, v);
    } else if (wrp == 1) {
        float4 v[8];
        const float4* r = (const float4*)(w2 + lane * 32);
#pragma unroll
        for (int q = 0; q < 8; q++) v[q] = r[q];
        split_store_row(sbuf + 5120 + lane * RS, 2560, v);
    }
    for (int i = tid; i < 1024; i += NW * 32) sbias[i] = bias[i];
    __syncthreads();

    // ---- build invariant fragments in registers ----
    const u32 s0 = smem_u32(sbuf);
    // W1^T B-frags: B[k=j1][n=i1] = W1[i1][j1] -> non-trans ldm on W1 rows (n,k)
    u32 w1Bh[2][4][2], w1Bl[2][4][2];   // [kt][nt][reg]
#pragma unroll
    for (int a = 0; a < 2; a++)          // n block 16a
#pragma unroll
        for (int b = 0; b < 2; b++) {    // k block 16b
            u32 r[4];
            ldm_x4(r, s0 + 0 + a * (16 * RS) + b * 32 + laneOff);
            w1Bh[b][2 * a][0] = r[0]; w1Bh[b][2 * a + 1][0] = r[1];
            w1Bh[b][2 * a][1] = r[2]; w1Bh[b][2 * a + 1][1] = r[3];
            ldm_x4(r, s0 + 2560 + a * (16 * RS) + b * 32 + laneOff);
            w1Bl[b][2 * a][0] = r[0]; w1Bl[b][2 * a + 1][0] = r[1];
            w1Bl[b][2 * a][1] = r[2]; w1Bl[b][2 * a + 1][1] = r[3];
        }
    // W2 A-frags: A[i2][j2] row-major -> non-trans ldm on W2 rows
    u32 w2Ah[2][2][4], w2Al[2][2][4];   // [mt][kt][4]
#pragma unroll
    for (int mt = 0; mt < 2; mt++)
#pragma unroll
        for (int kt = 0; kt < 2; kt++) {
            ldm_x4(w2Ah[mt][kt], s0 + 5120 + mt * (16 * RS) + kt * 32 + laneOff);
            ldm_x4(w2Al[mt][kt], s0 + 7680 + mt * (16 * RS) + kt * 32 + laneOff);
        }
    __syncthreads();   // all warps done reading warp0's buffer

    const int gw = blockIdx.x * NW + wrp;
    const int nw = gridDim.x * NW;

    for (int m = gw; m < rows; m += nw) {
        // ---- load X row (lane = j2), split, store hi/lo ----
        {
            float4 v[8];
            const float4* xr = (const float4*)(x + (size_t)m * 1024 + lane * 32);
#pragma unroll
            for (int q = 0; q < 8; q++) v[q] = xr[q];
            split_store_row(wbuf + XH + lane * RS, XL - XH, v);
        }
        __syncwarp();

        // ---- X A-frags ----
        u32 XAh[2][2][4], XAl[2][2][4];
#pragma unroll
        for (int mt = 0; mt < 2; mt++)
#pragma unroll
            for (int kt = 0; kt < 2; kt++) {
                ldm_x4(XAh[mt][kt], wbA + XH + mt * (16 * RS) + kt * 32 + laneOff);
                ldm_x4(XAl[mt][kt], wbA + XL + mt * (16 * RS) + kt * 32 + laneOff);
            }

        // ---- stage 1: T = X @ W1^T (3-term split) ----
        float acc[32];
#pragma unroll
        for (int i = 0; i < 32; i++) acc[i] = 0.f;
#pragma unroll
        for (int kt = 0; kt < 2; kt++)
#pragma unroll
            for (int mt = 0; mt < 2; mt++)
#pragma unroll
                for (int nt = 0; nt < 4; nt++) {
                    float* c = &acc[(mt * 4 + nt) * 4];
                    mma_bf16(c, XAh[mt][kt], w1Bh[kt][nt]);
                    mma_bf16(c, XAh[mt][kt], w1Bl[kt][nt]);
                    mma_bf16(c, XAl[mt][kt], w1Bh[kt][nt]);
                }

        // ---- split T, store row-major (j2 x i1) hi/lo ----
#pragma unroll
        for (int mt = 0; mt < 2; mt++)
#pragma unroll
            for (int nt = 0; nt < 4; nt++) {
                float* c = &acc[(mt * 4 + nt) * 4];
                u32 h01, l01, h23, l23;
                split2(c[0], c[1], h01, l01);
                split2(c[2], c[3], h23, l23);
                int off = (16 * mt + qr) * RS + (8 * nt + qc) * 2;
                *(u32*)(wbuf + TH + off) = h01;
                *(u32*)(wbuf + TL + off) = l01;
                off += 8 * RS;
                *(u32*)(wbuf + TH + off) = h23;
                *(u32*)(wbuf + TL + off) = l23;
            }
        __syncwarp();

        // ---- T B-frags (trans: B[k=j2][n=i1]) ----
        u32 TBh[2][4][2], TBl[2][4][2];
#pragma unroll
        for (int kt = 0; kt < 2; kt++)
#pragma unroll
            for (int b = 0; b < 2; b++) {
                u32 r[4];
                ldm_x4t(r, wbA + TH + kt * (16 * RS) + b * 32 + laneOff);
                TBh[kt][2 * b][0] = r[0]; TBh[kt][2 * b][1] = r[1];
                TBh[kt][2 * b + 1][0] = r[2]; TBh[kt][2 * b + 1][1] = r[3];
                ldm_x4t(r, wbA + TL + kt * (16 * RS) + b * 32 + laneOff);
                TBl[kt][2 * b][0] = r[0]; TBl[kt][2 * b][1] = r[1];
                TBl[kt][2 * b + 1][0] = r[2]; TBl[kt][2 * b + 1][1] = r[3];
            }

        // ---- stage 2: G = W2 @ T (3-term split) ----
        float acc2[32];
#pragma unroll
        for (int i = 0; i < 32; i++) acc2[i] = 0.f;
#pragma unroll
        for (int kt = 0; kt < 2; kt++)
#pragma unroll
            for (int mt = 0; mt < 2; mt++)
#pragma unroll
                for (int nt = 0; nt < 4; nt++) {
                    float* c = &acc2[(mt * 4 + nt) * 4];
                    mma_bf16(c, w2Ah[mt][kt], TBh[kt][nt]);
                    mma_bf16(c, w2Ah[mt][kt], TBl[kt][nt]);
                    mma_bf16(c, w2Al[mt][kt], TBh[kt][nt]);
                }
        __syncwarp();   // X/G overlay region free, T reads done

        // ---- store G fp32 (overlays X buffers), stride GS ----
#pragma unroll
        for (int mt = 0; mt < 2; mt++)
#pragma unroll
            for (int nt = 0; nt < 4; nt++) {
                float* c = &acc2[(mt * 4 + nt) * 4];
                int off = (16 * mt + qr) * GS + (8 * nt + qc) * 4;
                *(float2*)(wbuf + off) = make_float2(c[0], c[1]);
                *(float2*)(wbuf + off + 8 * GS) = make_float2(c[2], c[3]);
            }
        __syncwarp();

        // ---- final: gather ALL 32 G rows (8 passes x 4 rows), add bias, STG.128
        float* ob = out + (size_t)m * 1024;
        const int g4 = lane >> 3;          // 0..3
        const int h4 = (lane & 7) * 4;     // col base 0..28
#pragma unroll
        for (int it = 0; it < 8; it++) {
            int i2 = 4 * it + g4;          // covers all 32 rows
            float4 g = *(const float4*)(wbuf + i2 * GS + h4 * 4);
            const float4 b4 = *(const float4*)(&sbias[i2 * 32 + h4]);
            g.x += b4.x; g.y += b4.y; g.z += b4.z; g.w += b4.w;
            *(float4*)(ob + i2 * 32 + h4) = g;
        }
        __syncwarp();   // G region becomes X buffer next iteration
    }
}

extern "C" void kernel_launch(void* const* d_in, const int* in_sizes, int n_in,
                              void* d_out, int out_size) {
    const float* x    = (const float*)d_in[0];
    const float* w1   = (const float*)d_in[1];
    const float* w2   = (const float*)d_in[2];
    const float* bias = (const float*)d_in[3];
    float* out        = (float*)d_out;

    int rows = in_sizes[0] / 1024;    // 65536

    int grid = 296;                   // ~2 CTAs/SM persistent
    int maxg = (rows + NW - 1) / NW;
    if (grid > maxg) grid = maxg;
    kron_mma2_kernel<<<grid, NW * 32>>>(x, w1, w2, bias, out, rows);
}

// round 7
// speedup vs baseline: 5.1884x; 1.4818x over previous
#include <cuda_runtime.h>
#include <cuda_bf16.h>
#include <cstdint>

// y[m, i2*32+i1] = sum_{j2,j1} x[m,j2*32+j1] * W2[i2,j2] * W1[i1,j1] + bias
// Per row m (one warp):
//   Stage1: T[j2][i1] = X @ W1^T   (A = X frags loaded DIRECTLY from gmem,
//                                   B = W1^T frags in registers)
//   Stage2: G[i2][i1] = W2 @ T     (A = W2 frags in registers,
//                                   B = T frags via movmatrix — no smem!)
// mma.sync.m16n8k16 bf16, fp32 accuracy via 3-term hi/lo split.
// Main loop touches smem ONLY for the permuted bias table (acc2 init).

typedef unsigned int u32;

#define RS 80                 // weight staging row stride (bytes)
#define NW 4                  // warps per CTA

__shared__ __align__(16) char swts[10240];     // W1h@0 W1l@2560 W2h@5120 W2l@7680
__shared__ __align__(16) float2 pbias[512];    // [t*2+h][lane], frag-permuted

__device__ __forceinline__ u32 smem_u32(const void* p) {
    u32 a;
    asm("{ .reg .u64 t; cvta.to.shared.u64 t, %1; cvt.u32.u64 %0, t; }"
        : "=r"(a) : "l"(p));
    return a;
}
__device__ __forceinline__ void ldm_x4(u32* r, u32 addr) {
    asm volatile("ldmatrix.sync.aligned.m8n8.x4.shared.b16 {%0,%1,%2,%3}, [%4];"
                 : "=r"(r[0]), "=r"(r[1]), "=r"(r[2]), "=r"(r[3]) : "r"(addr));
}
__device__ __forceinline__ u32 movm(u32 v) {
    u32 d;
    asm("movmatrix.sync.aligned.m8n8.trans.b16 %0, %1;" : "=r"(d) : "r"(v));
    return d;
}
__device__ __forceinline__ void mma_bf16(float* c, const u32* a, const u32* b) {
    asm volatile(
        "mma.sync.aligned.m16n8k16.row.col.f32.bf16.bf16.f32 "
        "{%0,%1,%2,%3}, {%4,%5,%6,%7}, {%8,%9}, {%0,%1,%2,%3};"
        : "+f"(c[0]), "+f"(c[1]), "+f"(c[2]), "+f"(c[3])
        : "r"(a[0]), "r"(a[1]), "r"(a[2]), "r"(a[3]), "r"(b[0]), "r"(b[1]));
}
// h = bf16x2(a -> low half, b -> high half); l = residuals
__device__ __forceinline__ void split2(float a, float b, u32& h, u32& l) {
    asm("cvt.rn.bf16x2.f32 %0, %1, %2;" : "=r"(h) : "f"(b), "f"(a));
    float ha = __uint_as_float(h << 16);
    float hb = __uint_as_float(h & 0xFFFF0000u);
    float ra = a - ha, rb = b - hb;
    asm("cvt.rn.bf16x2.f32 %0, %1, %2;" : "=r"(l) : "f"(rb), "f"(ra));
}
// split a 32-float row (8 float4), store hi/lo 64B rows at rowPtr / rowPtr+2560
__device__ __forceinline__ void split_store_row(char* rowPtr, const float4* v) {
    u32 hw[16], lw[16];
#pragma unroll
    for (int q = 0; q < 8; q++) {
        split2(v[q].x, v[q].y, hw[2 * q], lw[2 * q]);
        split2(v[q].z, v[q].w, hw[2 * q + 1], lw[2 * q + 1]);
    }
#pragma unroll
    for (int c = 0; c < 4; c++) {
        *(uint4*)(rowPtr + c * 16) =
            make_uint4(hw[4 * c], hw[4 * c + 1], hw[4 * c + 2], hw[4 * c + 3]);
        *(uint4*)(rowPtr + 2560 + c * 16) =
            make_uint4(lw[4 * c], lw[4 * c + 1], lw[4 * c + 2], lw[4 * c + 3]);
    }
}

__global__ void __launch_bounds__(NW * 32)
kron_mma3_kernel(const float* __restrict__ x,
                 const float* __restrict__ w1,
                 const float* __restrict__ w2,
                 const float* __restrict__ bias,
                 float* __restrict__ out,
                 int rows)
{
    const int tid  = threadIdx.x;
    const int lane = tid & 31;
    const int wrp  = tid >> 5;

    const int lq  = lane >> 2;          // l/4: frag row within 8-block
    const int lr2 = (lane & 3) << 1;    // 2*(l%4): frag col pair base

    // ldmatrix lane offset for weight-frag construction
    const u32 laneOff = ((lane & 7) + 8 * ((lane >> 3) & 1)) * RS +
                        ((lane >> 4) << 4);

    // ---- one-time: stage split W1/W2 into smem ----
    if (wrp == 0) {
        float4 v[8];
        const float4* r = (const float4*)(w1 + lane * 32);
#pragma unroll
        for (int q = 0; q < 8; q++) v[q] = r[q];
        split_store_row(swts + 0 + lane * RS, v);
    } else if (wrp == 1) {
        float4 v[8];
        const float4* r = (const float4*)(w2 + lane * 32);
#pragma unroll
        for (int q = 0; q < 8; q++) v[q] = r[q];
        split_store_row(swts + 5120 + lane * RS, v);
    }
    // permuted bias: pbias[(t*2+h)*32 + lane] = bias pair at frag position
    for (int c = wrp; c < 16; c += NW) {
        int t = c >> 1, h = c & 1;
        int mt = t >> 2, nt = t & 3;
        int row = 16 * mt + lq + 8 * h;
        int col = 8 * nt + lr2;
        pbias[c * 32 + lane] = make_float2(bias[row * 32 + col],
                                           bias[row * 32 + col + 1]);
    }
    __syncthreads();

    // ---- invariant weight fragments in registers ----
    const u32 s0 = smem_u32(swts);
    u32 w1Bh[2][4][2], w1Bl[2][4][2];   // B-frags of W1^T: [kt][nt][b0,b1]
#pragma unroll
    for (int a = 0; a < 2; a++)          // i1 (n) 16-block
#pragma unroll
        for (int b = 0; b < 2; b++) {    // j1 (k) 16-block
            u32 r[4];
            ldm_x4(r, s0 + 0 + a * (16 * RS) + b * 32 + laneOff);
            w1Bh[b][2 * a][0] = r[0]; w1Bh[b][2 * a + 1][0] = r[1];
            w1Bh[b][2 * a][1] = r[2]; w1Bh[b][2 * a + 1][1] = r[3];
            ldm_x4(r, s0 + 2560 + a * (16 * RS) + b * 32 + laneOff);
            w1Bl[b][2 * a][0] = r[0]; w1Bl[b][2 * a + 1][0] = r[1];
            w1Bl[b][2 * a][1] = r[2]; w1Bl[b][2 * a + 1][1] = r[3];
        }
    u32 w2Ah[2][2][4], w2Al[2][2][4];   // A-frags of W2: [mt][kt][4]
#pragma unroll
    for (int mt = 0; mt < 2; mt++)
#pragma unroll
        for (int kt = 0; kt < 2; kt++) {
            ldm_x4(w2Ah[mt][kt], s0 + 5120 + mt * (16 * RS) + kt * 32 + laneOff);
            ldm_x4(w2Al[mt][kt], s0 + 7680 + mt * (16 * RS) + kt * 32 + laneOff);
        }
    __syncthreads();

    const int gw = blockIdx.x * NW + wrp;
    const int nw = gridDim.x * NW;

    for (int m = gw; m < rows; m += nw) {
        const float* xb = x + (size_t)m * 1024;

        // ---- X A-frags straight from gmem (16x LDG.64, 100% sectors) ----
        u32 XAh[2][2][4], XAl[2][2][4];
#pragma unroll
        for (int mt = 0; mt < 2; mt++)
#pragma unroll
            for (int kt = 0; kt < 2; kt++) {
                int base = (16 * mt + lq) * 32 + 16 * kt + lr2;
                float2 p0 = *(const float2*)(xb + base);
                float2 p1 = *(const float2*)(xb + base + 256);      // +8 rows
                float2 p2 = *(const float2*)(xb + base + 8);        // +8 cols
                float2 p3 = *(const float2*)(xb + base + 264);
                split2(p0.x, p0.y, XAh[mt][kt][0], XAl[mt][kt][0]);
                split2(p1.x, p1.y, XAh[mt][kt][1], XAl[mt][kt][1]);
                split2(p2.x, p2.y, XAh[mt][kt][2], XAl[mt][kt][2]);
                split2(p3.x, p3.y, XAh[mt][kt][3], XAl[mt][kt][3]);
            }

        // ---- stage 1: T = X @ W1^T (3-term split) ----
        float acc[32];
#pragma unroll
        for (int i = 0; i < 32; i++) acc[i] = 0.f;
#pragma unroll
        for (int kt = 0; kt < 2; kt++)
#pragma unroll
            for (int mt = 0; mt < 2; mt++)
#pragma unroll
                for (int nt = 0; nt < 4; nt++) {
                    float* c = &acc[(mt * 4 + nt) * 4];
                    mma_bf16(c, XAh[mt][kt], w1Bh[kt][nt]);
                    mma_bf16(c, XAh[mt][kt], w1Bl[kt][nt]);
                    mma_bf16(c, XAl[mt][kt], w1Bh[kt][nt]);
                }

        // ---- T c-frags -> stage-2 B-frags via movmatrix (in registers) ----
        u32 TBh[2][4][2], TBl[2][4][2];
#pragma unroll
        for (int kt = 0; kt < 2; kt++)        // stage-1 mt == stage-2 kt
#pragma unroll
            for (int nt = 0; nt < 4; nt++) {
                float* c = &acc[(kt * 4 + nt) * 4];
                u32 h01, l01, h23, l23;
                split2(c[0], c[1], h01, l01);
                split2(c[2], c[3], h23, l23);
                TBh[kt][nt][0] = movm(h01);   // k-rows 0..7 of this 16-block
                TBh[kt][nt][1] = movm(h23);   // k-rows 8..15
                TBl[kt][nt][0] = movm(l01);
                TBl[kt][nt][1] = movm(l23);
            }

        // ---- stage 2: G = W2 @ T, acc init = bias (coalesced LDS.64) ----
        float acc2[32];
#pragma unroll
        for (int t = 0; t < 8; t++) {
            float2 b0 = pbias[(t * 2) * 32 + lane];
            float2 b1 = pbias[(t * 2 + 1) * 32 + lane];
            acc2[t * 4 + 0] = b0.x; acc2[t * 4 + 1] = b0.y;
            acc2[t * 4 + 2] = b1.x; acc2[t * 4 + 3] = b1.y;
        }
#pragma unroll
        for (int kt = 0; kt < 2; kt++)
#pragma unroll
            for (int mt = 0; mt < 2; mt++)
#pragma unroll
                for (int nt = 0; nt < 4; nt++) {
                    float* c = &acc2[(mt * 4 + nt) * 4];
                    mma_bf16(c, w2Ah[mt][kt], TBh[kt][nt]);
                    mma_bf16(c, w2Ah[mt][kt], TBl[kt][nt]);
                    mma_bf16(c, w2Al[mt][kt], TBh[kt][nt]);
                }

        // ---- store G directly from c-frags (16x STG.64, 100% sectors) ----
        float* ob = out + (size_t)m * 1024;
#pragma unroll
        for (int mt = 0; mt < 2; mt++)
#pragma unroll
            for (int nt = 0; nt < 4; nt++) {
                float* c = &acc2[(mt * 4 + nt) * 4];
                int base = (16 * mt + lq) * 32 + 8 * nt + lr2;
                *(float2*)(ob + base) = make_float2(c[0], c[1]);
                *(float2*)(ob + base + 256) = make_float2(c[2], c[3]);
            }
    }
}

extern "C" void kernel_launch(void* const* d_in, const int* in_sizes, int n_in,
                              void* d_out, int out_size) {
    const float* x    = (const float*)d_in[0];
    const float* w1   = (const float*)d_in[1];
    const float* w2   = (const float*)d_in[2];
    const float* bias = (const float*)d_in[3];
    float* out        = (float*)d_out;

    int rows = in_sizes[0] / 1024;    // 65536

    int grid = 592;                   // up to 4 CTAs/SM, grid-stride persistent
    int maxg = (rows + NW - 1) / NW;
    if (grid > maxg) grid = maxg;
    kron_mma3_kernel<<<grid, NW * 32>>>(x, w1, w2, bias, out, rows);
}

// round 9
// speedup vs baseline: 5.4512x; 1.0507x over previous
#include <cuda_runtime.h>
#include <cuda_bf16.h>
#include <cstdint>

// y[m, i2*32+i1] = sum_{j2,j1} x[m,j2*32+j1] * W2[i2,j2] * W1[i1,j1] + bias
// Per row m (one warp):
//   Stage1: T = X @ W1^T  (A = X frags straight from gmem via LDG.128 +
//                          k-permutation sigma; B = W1^T frags in regs,
//                          staged with sigma on k and tau on n)
//   Stage2: G = W2 @ T    (A = W2 frags in regs; B = T via movmatrix)
// tau makes each lane's outputs contiguous 32B -> coalesced STG.128.
// mma.sync.m16n8k16 bf16, fp32 accuracy via 3-term hi/lo split.

typedef unsigned int u32;

#define RS 80                 // weight staging row stride (bytes)
#define NW 4                  // warps per CTA

__shared__ __align__(16) char swts[10240];     // W1h@0 W1l@2560 W2h@5120 W2l@7680
__shared__ __align__(16) float4 pbias4[256];   // [t][lane] tau/frag-permuted bias

__device__ __forceinline__ u32 smem_u32(const void* p) {
    u32 a;
    asm("{ .reg .u64 t; cvta.to.shared.u64 t, %1; cvt.u32.u64 %0, t; }"
        : "=r"(a) : "l"(p));
    return a;
}
__device__ __forceinline__ void ldm_x4(u32* r, u32 addr) {
    asm volatile("ldmatrix.sync.aligned.m8n8.x4.shared.b16 {%0,%1,%2,%3}, [%4];"
                 : "=r"(r[0]), "=r"(r[1]), "=r"(r[2]), "=r"(r[3]) : "r"(addr));
}
__device__ __forceinline__ u32 movm(u32 v) {
    u32 d;
    asm("movmatrix.sync.aligned.m8n8.trans.b16 %0, %1;" : "=r"(d) : "r"(v));
    return d;
}
__device__ __forceinline__ void mma_bf16(float* c, const u32* a, const u32* b) {
    asm volatile(
        "mma.sync.aligned.m16n8k16.row.col.f32.bf16.bf16.f32 "
        "{%0,%1,%2,%3}, {%4,%5,%6,%7}, {%8,%9}, {%0,%1,%2,%3};"
        : "+f"(c[0]), "+f"(c[1]), "+f"(c[2]), "+f"(c[3])
        : "r"(a[0]), "r"(a[1]), "r"(a[2]), "r"(a[3]), "r"(b[0]), "r"(b[1]));
}
// h = bf16x2(a -> low half, b -> high half); l = residuals
__device__ __forceinline__ void split2(float a, float b, u32& h, u32& l) {
    asm("cvt.rn.bf16x2.f32 %0, %1, %2;" : "=r"(h) : "f"(b), "f"(a));
    float ha = __uint_as_float(h << 16);
    float hb = __uint_as_float(h & 0xFFFF0000u);
    float ra = a - ha, rb = b - hb;
    asm("cvt.rn.bf16x2.f32 %0, %1, %2;" : "=r"(l) : "f"(rb), "f"(ra));
}
// split 32 floats, store hi/lo 64B rows at rowPtr / rowPtr+2560
__device__ __forceinline__ void split_store_row(char* rowPtr, const float* v) {
    u32 hw[16], lw[16];
#pragma unroll
    for (int p = 0; p < 16; p++) split2(v[2 * p], v[2 * p + 1], hw[p], lw[p]);
#pragma unroll
    for (int c = 0; c < 4; c++) {
        *(uint4*)(rowPtr + c * 16) =
            make_uint4(hw[4 * c], hw[4 * c + 1], hw[4 * c + 2], hw[4 * c + 3]);
        *(uint4*)(rowPtr + 2560 + c * 16) =
            make_uint4(lw[4 * c], lw[4 * c + 1], lw[4 * c + 2], lw[4 * c + 3]);
    }
}
// sigma: frag k-pos (within 16-block) -> physical col (within 16-block)
__device__ __forceinline__ int sigma16(int k) {
    return 4 * ((k & 7) >> 1) + 2 * (k >> 3) + (k & 1);
}
// tau: frag n-pos -> physical i1 col (involution, global 0..31)
__device__ __forceinline__ int tau32(int n) {
    return 8 * ((n & 7) >> 1) + 2 * (n >> 3) + (n & 1);
}

__global__ void __launch_bounds__(NW * 32)
kron_mma5_kernel(const float* __restrict__ x,
                 const float* __restrict__ w1,
                 const float* __restrict__ w2,
                 const float* __restrict__ bias,
                 float* __restrict__ out,
                 int rows)
{
    const int tid  = threadIdx.x;
    const int lane = tid & 31;
    const int wrp  = tid >> 5;

    const int lq = lane >> 2;           // frag row within 8-block
    const int lr = lane & 3;            // quad index r

    const u32 laneOff = ((lane & 7) + 8 * ((lane >> 3) & 1)) * RS +
                        ((lane >> 4) << 4);

    // ---- one-time staging ----
    if (wrp == 0) {
        // FIX (R8 bug was row/col transposed): rows of M1 are n-positions nu,
        // cols are k-positions c:  M1[nu][c] = W1[tau(nu)][16*(c>>4)+sigma(c&15)]
        float v[32];
        const float* wrow = w1 + tau32(lane) * 32;    // lane = nu
#pragma unroll
        for (int c = 0; c < 32; c++)
            v[c] = wrow[16 * (c >> 4) + sigma16(c & 15)];
        split_store_row(swts + 0 + lane * RS, v);
    } else if (wrp == 1) {
        // M2[i2][j2] = W2 row-major (identity perms on stage-2 M and K)
        float v[32];
        const float4* r = (const float4*)(w2 + lane * 32);
#pragma unroll
        for (int q = 0; q < 8; q++) {
            float4 t = r[q];
            v[4*q] = t.x; v[4*q+1] = t.y; v[4*q+2] = t.z; v[4*q+3] = t.w;
        }
        split_store_row(swts + 5120 + lane * RS, v);
    }
    // pbias4[t=mt*4+nt][lane]: physical (row 16mt+lq(+8), col 8*lr+2*nt, +1)
    for (int t = wrp; t < 8; t += NW) {
        int mt = t >> 2, nt = t & 3;
        int row = 16 * mt + lq;
        int col = 8 * lr + 2 * nt;
        pbias4[t * 32 + lane] =
            make_float4(bias[row * 32 + col], bias[row * 32 + col + 1],
                        bias[(row + 8) * 32 + col], bias[(row + 8) * 32 + col + 1]);
    }
    __syncthreads();

    // ---- invariant weight fragments in registers ----
    const u32 s0 = smem_u32(swts);
    u32 w1Bh[2][4][2], w1Bl[2][4][2];   // [kt][nt][reg]
#pragma unroll
    for (int a = 0; a < 2; a++)
#pragma unroll
        for (int b = 0; b < 2; b++) {
            u32 r[4];
            ldm_x4(r, s0 + 0 + a * (16 * RS) + b * 32 + laneOff);
            w1Bh[b][2*a][0] = r[0]; w1Bh[b][2*a+1][0] = r[1];
            w1Bh[b][2*a][1] = r[2]; w1Bh[b][2*a+1][1] = r[3];
            ldm_x4(r, s0 + 2560 + a * (16 * RS) + b * 32 + laneOff);
            w1Bl[b][2*a][0] = r[0]; w1Bl[b][2*a+1][0] = r[1];
            w1Bl[b][2*a][1] = r[2]; w1Bl[b][2*a+1][1] = r[3];
        }
    u32 w2Ah[2][2][4], w2Al[2][2][4];   // [mt][kt][4]
#pragma unroll
    for (int mt = 0; mt < 2; mt++)
#pragma unroll
        for (int kt = 0; kt < 2; kt++) {
            ldm_x4(w2Ah[mt][kt], s0 + 5120 + mt * (16 * RS) + kt * 32 + laneOff);
            ldm_x4(w2Al[mt][kt], s0 + 7680 + mt * (16 * RS) + kt * 32 + laneOff);
        }
    __syncthreads();

    const int gw = blockIdx.x * NW + wrp;
    const int nw = gridDim.x * NW;

    for (int m = gw; m < rows; m += nw) {
        const float* xb = x + (size_t)m * 1024;

        // ---- X A-frags: 8 LDG.128; sigma makes lane's own float4 = its frag
        // words: (v.x,v.y) -> k-pair 2r ; (v.z,v.w) -> k-pair 2r+8 ----
        float4 xv[2][2][2];   // [mt][kt][h]
#pragma unroll
        for (int mt = 0; mt < 2; mt++)
#pragma unroll
            for (int kt = 0; kt < 2; kt++) {
                int base = (16 * mt + lq) * 32 + 16 * kt + 4 * lr;
                xv[mt][kt][0] = *(const float4*)(xb + base);
                xv[mt][kt][1] = *(const float4*)(xb + base + 256);  // +8 rows
            }
        u32 XAh[2][2][4], XAl[2][2][4];
#pragma unroll
        for (int mt = 0; mt < 2; mt++)
#pragma unroll
            for (int kt = 0; kt < 2; kt++) {
                float4 u = xv[mt][kt][0], v = xv[mt][kt][1];
                split2(u.x, u.y, XAh[mt][kt][0], XAl[mt][kt][0]);  // a0
                split2(v.x, v.y, XAh[mt][kt][1], XAl[mt][kt][1]);  // a1
                split2(u.z, u.w, XAh[mt][kt][2], XAl[mt][kt][2]);  // a2
                split2(v.z, v.w, XAh[mt][kt][3], XAl[mt][kt][3]);  // a3
            }

        // ---- stage 1: T = X @ W1^T (3-term split) ----
        float acc[32];
#pragma unroll
        for (int i = 0; i < 32; i++) acc[i] = 0.f;
#pragma unroll
        for (int kt = 0; kt < 2; kt++)
#pragma unroll
            for (int mt = 0; mt < 2; mt++)
#pragma unroll
                for (int nt = 0; nt < 4; nt++) {
                    float* c = &acc[(mt * 4 + nt) * 4];
                    mma_bf16(c, XAh[mt][kt], w1Bh[kt][nt]);
                    mma_bf16(c, XAh[mt][kt], w1Bl[kt][nt]);
                    mma_bf16(c, XAl[mt][kt], w1Bh[kt][nt]);
                }

        // ---- T c-frags -> stage-2 B-frags via movmatrix ----
        u32 TBh[2][4][2], TBl[2][4][2];
#pragma unroll
        for (int kt = 0; kt < 2; kt++)
#pragma unroll
            for (int nt = 0; nt < 4; nt++) {
                float* c = &acc[(kt * 4 + nt) * 4];
                u32 h01, l01, h23, l23;
                split2(c[0], c[1], h01, l01);
                split2(c[2], c[3], h23, l23);
                TBh[kt][nt][0] = movm(h01);
                TBh[kt][nt][1] = movm(h23);
                TBl[kt][nt][0] = movm(l01);
                TBl[kt][nt][1] = movm(l23);
            }

        // ---- stage 2: G = W2 @ T, acc init = bias (8 LDS.128) ----
        float acc2[32];
#pragma unroll
        for (int t = 0; t < 8; t++) {
            float4 b4 = pbias4[t * 32 + lane];
            acc2[t*4+0] = b4.x; acc2[t*4+1] = b4.y;
            acc2[t*4+2] = b4.z; acc2[t*4+3] = b4.w;
        }
#pragma unroll
        for (int kt = 0; kt < 2; kt++)
#pragma unroll
            for (int mt = 0; mt < 2; mt++)
#pragma unroll
                for (int nt = 0; nt < 4; nt++) {
                    float* c = &acc2[(mt * 4 + nt) * 4];
                    mma_bf16(c, w2Ah[mt][kt], TBh[kt][nt]);
                    mma_bf16(c, w2Ah[mt][kt], TBl[kt][nt]);
                    mma_bf16(c, w2Al[mt][kt], TBh[kt][nt]);
                }

        // ---- store: tau gives each lane 32B contiguous per row -> STG.128 ----
        // physical col of frag (nt, pair-elem e) = 8*lr + 2*nt + e
        float* ob = out + (size_t)m * 1024;
#pragma unroll
        for (int mt = 0; mt < 2; mt++)
#pragma unroll
            for (int h = 0; h < 2; h++) {
                int base = (16 * mt + 8 * h + lq) * 32 + 8 * lr;
                *(float4*)(ob + base) =
                    make_float4(acc2[(mt*4+0)*4 + 2*h], acc2[(mt*4+0)*4 + 2*h + 1],
                                acc2[(mt*4+1)*4 + 2*h], acc2[(mt*4+1)*4 + 2*h + 1]);
                *(float4*)(ob + base + 4) =
                    make_float4(acc2[(mt*4+2)*4 + 2*h], acc2[(mt*4+2)*4 + 2*h + 1],
                                acc2[(mt*4+3)*4 + 2*h], acc2[(mt*4+3)*4 + 2*h + 1]);
            }
    }
}

extern "C" void kernel_launch(void* const* d_in, const int* in_sizes, int n_in,
                              void* d_out, int out_size) {
    const float* x    = (const float*)d_in[0];
    const float* w1   = (const float*)d_in[1];
    const float* w2   = (const float*)d_in[2];
    const float* bias = (const float*)d_in[3];
    float* out        = (float*)d_out;

    int rows = in_sizes[0] / 1024;    // 65536

    int grid = 592;                   // 4 CTAs/SM, grid-stride persistent
    int maxg = (rows + NW - 1) / NW;
    if (grid > maxg) grid = maxg;
    kron_mma5_kernel<<<grid, NW * 32>>>(x, w1, w2, bias, out, rows);
}